// round 6
// baseline (speedup 1.0000x reference)
#include <cuda_runtime.h>
#include <math.h>

#define NPART 512
#define NB    16
#define HIDN  100
#define WPB   4            // warps per block (main kernel)
#define NI    2            // particles i per warp
#define TPB   128

typedef unsigned long long u64;

// ---- device-global scratch (no allocations allowed) ----
// pair-interleaved packed per-j constants; gP*[b*256+idx] covers j=2*idx,2*idx+1
// gP0 = { -y pair, -x pair }    gP1 = { ml2e pair, mc pair }
// gP2 = { md pair, tau/2pi pair } gP3 = { 1/sig^2 pair, -c/2 pair }
__device__ ulonglong2 gP0[NB * NPART / 2];
__device__ ulonglong2 gP1[NB * NPART / 2];
__device__ ulonglong2 gP2[NB * NPART / 2];
__device__ ulonglong2 gP3[NB * NPART / 2];
__device__ float      gW2T[6 * HIDN];      // gW2T[m*HIDN+k] = W2[k*6+m]

__device__ __forceinline__ float ex2f(float x) {
    float y; asm("ex2.approx.ftz.f32 %0, %1;" : "=f"(y) : "f"(x)); return y;
}
__device__ __forceinline__ float rsq_a(float x) {
    float y; asm("rsqrt.approx.ftz.f32 %0, %1;" : "=f"(y) : "f"(x)); return y;
}
__device__ __forceinline__ float rcp_a(float x) {
    float y; asm("rcp.approx.ftz.f32 %0, %1;" : "=f"(y) : "f"(x)); return y;
}

// ---- packed f32x2 helpers (sm_100+) ----
__device__ __forceinline__ u64 pk2(float lo, float hi) {
    u64 d; asm("mov.b64 %0, {%1, %2};" : "=l"(d) : "f"(lo), "f"(hi)); return d;
}
__device__ __forceinline__ void upk2(u64 v, float& lo, float& hi) {
    asm("mov.b64 {%0, %1}, %2;" : "=f"(lo), "=f"(hi) : "l"(v));
}
__device__ __forceinline__ u64 fma2(u64 a, u64 b, u64 c) {
    u64 d; asm("fma.rn.f32x2 %0, %1, %2, %3;" : "=l"(d) : "l"(a), "l"(b), "l"(c)); return d;
}
__device__ __forceinline__ u64 mul2(u64 a, u64 b) {
    u64 d; asm("mul.rn.f32x2 %0, %1, %2;" : "=l"(d) : "l"(a), "l"(b)); return d;
}
__device__ __forceinline__ u64 add2(u64 a, u64 b) {
    u64 d; asm("add.rn.f32x2 %0, %1, %2;" : "=l"(d) : "l"(a), "l"(b)); return d;
}
__device__ __forceinline__ u64 ex2p(u64 a) {
    float lo, hi; upk2(a, lo, hi);
    return pk2(ex2f(lo), ex2f(hi));
}
__device__ __forceinline__ u64 rsqp(u64 a) {
    float lo, hi; upk2(a, lo, hi);
    return pk2(rsq_a(lo), rsq_a(hi));
}

struct Acc { u64 vyp, vx, F, G, Gxx, Gyy; };

// per-pair vortex interaction (packed 2 j's). Accumulates vyp = +Sum F*dx
// (vy = -vyp, negated in feature assembly).
// q1 = {ml2e, mc}, q2 = {md, t2p}, q3 = {is2, -c/2}, nddv = {-d}
__device__ __forceinline__ void pair_body(
    u64 yi2, u64 xi2, const ulonglong2& q0, const ulonglong2& q1,
    const ulonglong2& q2, const ulonglong2& q3, u64 nddv, Acc& a,
    u64 nones, u64 eps2)
{
    u64 dy   = add2(yi2, q0.x);                // yi - yj
    u64 dx   = add2(xi2, q0.y);                // xi - xj
    u64 sq   = fma2(dy, dy, mul2(dx, dx));
    u64 s    = add2(sq, eps2);
    u64 rs   = rsqp(s);                        // 1/sqrt(s)
    u64 r    = mul2(s, rs);                    // sqrt(s)
    u64 ivs  = mul2(rs, rs);                   // 1/s
    u64 mdsq = mul2(q2.x, sq);                 // md*sq (log2 units)
    u64 arg2 = fma2(q1.y, r, mdsq);            // mc*r + md*sq
    u64 arg12= fma2(q1.x, sq, arg2);           // + ml2e*sq
    u64 e2   = ex2p(arg2);                     // exp(-c r - d sq)
    u64 e12  = ex2p(arg12);                    // e1*e2 (== e2 when j==i)
    u64 gh   = fma2(e12, nones, e2);           // (1-e1)*e2 = e2 - e12
    u64 A    = mul2(q2.y, ivs);                // tau/(2 pi s)
    u64 F    = mul2(A, gh);                    // falloff
    u64 t1   = mul2(q3.x, e12);                // is2*e1*e2
    u64 mivs = fma2(ivs, nones, nddv);         // -1/s - d
    u64 t2n  = fma2(q3.y, rs, mivs);           // -(c/(2r) + d + 1/s)
    u64 inner= fma2(gh, t2n, t1);              // t1 - gh*t2
    u64 Fp   = mul2(A, inner);                 // dF/d(sq)
    u64 G2   = add2(Fp, Fp);
    a.vyp = fma2(F, dx, a.vyp);
    a.vx  = fma2(F, dy, a.vx);
    a.F   = add2(a.F, F);
    u64 gdy = mul2(G2, dy);
    u64 gdx = mul2(G2, dx);
    a.G   = fma2(gdy, dx, a.G);
    a.Gxx = fma2(gdx, dx, a.Gxx);
    a.Gyy = fma2(gdy, dy, a.Gyy);
}

// ---- precompute kernel: packs per-particle constants + W2 transpose ----
__global__ __launch_bounds__(TPB)
void prep_kernel(const float* __restrict__ inp, const float* __restrict__ W2)
{
    const float L2E    = 1.4426950408889634f;
    const float INV2PI = 0.15915494309189535f;
    int p = blockIdx.x * blockDim.x + threadIdx.x;   // 0..8191
    if (p < NB * NPART) {
        float y   = inp[p * 6 + 0];
        float x   = inp[p * 6 + 1];
        float tau = inp[p * 6 + 2];
        float sig = inp[p * 6 + 3];
        float c   = inp[p * 6 + 4];
        float d   = inp[p * 6 + 5];
        float is2 = rcp_a(sig * sig);
        int idx = p >> 1;                             // global pair index
        int o   = p & 1;
        float* f0 = (float*)gP0;
        float* f1 = (float*)gP1;
        float* f2 = (float*)gP2;
        float* f3 = (float*)gP3;
        f0[idx * 4 + 0 + o] = -y;
        f0[idx * 4 + 2 + o] = -x;
        f1[idx * 4 + 0 + o] = -is2 * L2E;   // ml2e
        f1[idx * 4 + 2 + o] = -c * L2E;     // mc
        f2[idx * 4 + 0 + o] = -d * L2E;     // md
        f2[idx * 4 + 2 + o] = tau * INV2PI; // t2p
        f3[idx * 4 + 0 + o] = is2;
        f3[idx * 4 + 2 + o] = -0.5f * c;    // nhc
    }
    if (p < HIDN * 6) {
        int k = p / 6, m = p % 6;
        gW2T[m * HIDN + k] = W2[p];
    }
}

// ---- main kernel: no shared memory, no syncthreads ----
__global__ __launch_bounds__(TPB, 8)
void vortex_main_kernel(const float* __restrict__ inp,
                        const float* __restrict__ W1,
                        const float* __restrict__ b1,
                        const float* __restrict__ b2,
                        float* __restrict__ out)
{
    const int tid  = threadIdx.x;
    const int ipb  = WPB * NI;                 // 8 i's per block
    const int bpb  = NPART / ipb;              // 64 blocks per batch
    const int b    = blockIdx.x / bpb;
    const int ig   = blockIdx.x % bpb;
    const int warp = tid >> 5;
    const int lane = tid & 31;
    const int i0   = ig * ipb + warp * NI;
    const int i1   = i0 + 1;

    const float LN2 = 0.6931471805599453f;

    const float* pA = inp + ((size_t)b * NPART + i0) * 6;
    const float* pB = inp + ((size_t)b * NPART + i1) * 6;
    const float yiA = __ldg(pA + 0), xiA = __ldg(pA + 1);
    const float yiB = __ldg(pB + 0), xiB = __ldg(pB + 1);

    const ulonglong2* __restrict__ P0 = gP0 + (size_t)b * (NPART / 2);
    const ulonglong2* __restrict__ P1 = gP1 + (size_t)b * (NPART / 2);
    const ulonglong2* __restrict__ P2 = gP2 + (size_t)b * (NPART / 2);
    const ulonglong2* __restrict__ P3 = gP3 + (size_t)b * (NPART / 2);

    const u64 yA = pk2(yiA, yiA), xA = pk2(xiA, xiA);
    const u64 yB = pk2(yiB, yiB), xB = pk2(xiB, xiB);
    const u64 nones = pk2(-1.0f, -1.0f);
    const u64 eps2  = pk2(1e-6f, 1e-6f);
    const u64 pln2  = pk2(LN2, LN2);

    Acc accA = {0,0,0,0,0,0};
    Acc accB = {0,0,0,0,0,0};

    #pragma unroll 1
    for (int jj = 0; jj < NPART / 64; ++jj) {
        int idx = jj * 32 + lane;
        ulonglong2 q0 = P0[idx];
        ulonglong2 q1 = P1[idx];
        ulonglong2 q2 = P2[idx];
        ulonglong2 q3 = P3[idx];
        u64 nddv = mul2(q2.x, pln2);           // -d = md * ln2
        pair_body(yA, xA, q0, q1, q2, q3, nddv, accA, nones, eps2);
        pair_body(yB, xB, q0, q1, q2, q3, nddv, accB, nones, eps2);
    }

    // ---- horizontal add of packed halves, then warp butterfly reduce ----
    float red[12];
    {
        float l, h;
        upk2(accA.vyp, l, h); red[0]  = l + h;
        upk2(accA.vx,  l, h); red[1]  = l + h;
        upk2(accA.F,   l, h); red[2]  = l + h;
        upk2(accA.G,   l, h); red[3]  = l + h;
        upk2(accA.Gxx, l, h); red[4]  = l + h;
        upk2(accA.Gyy, l, h); red[5]  = l + h;
        upk2(accB.vyp, l, h); red[6]  = l + h;
        upk2(accB.vx,  l, h); red[7]  = l + h;
        upk2(accB.F,   l, h); red[8]  = l + h;
        upk2(accB.G,   l, h); red[9]  = l + h;
        upk2(accB.Gxx, l, h); red[10] = l + h;
        upk2(accB.Gyy, l, h); red[11] = l + h;
    }
    #pragma unroll
    for (int o = 16; o; o >>= 1) {
        #pragma unroll
        for (int m = 0; m < 12; ++m)
            red[m] += __shfl_xor_sync(0xffffffffu, red[m], o);
    }

    // per-i scalars (loaded late to keep mainloop registers lean; L1/L2 hit)
    const float tauA = __ldg(pA + 2), sigA = __ldg(pA + 3);
    const float cA   = __ldg(pA + 4), dA   = __ldg(pA + 5);
    const float tauB = __ldg(pB + 2), sigB = __ldg(pB + 3);
    const float cB   = __ldg(pB + 4), dB   = __ldg(pB + 5);

    // features: tau, sig, c, d, vy, vx, dvy/dy, dvy/dx, dvx/dy, dvx/dx
    float featA[10], featB[10];
    featA[0] = tauA;    featA[1] = sigA;  featA[2] = cA;  featA[3] = dA;
    featA[4] = -red[0];            // vy = -Sum F dx
    featA[5] = red[1];
    featA[6] = -red[3];            // dvy/dy
    featA[7] = -(red[4] + red[2]); // dvy/dx
    featA[8] = red[5] + red[2];    // dvx/dy
    featA[9] = red[3];             // dvx/dx
    featB[0] = tauB;    featB[1] = sigB;  featB[2] = cB;  featB[3] = dB;
    featB[4] = -red[6];
    featB[5] = red[7];
    featB[6] = -red[9];
    featB[7] = -(red[10] + red[8]);
    featB[8] = red[11] + red[8];
    featB[9] = red[9];

    // ---- MLP 10 -> 100 (LeakyReLU 0.1) -> 6, weights via L1-hot LDG ----
    float poA[6] = {0,0,0,0,0,0};
    float poB[6] = {0,0,0,0,0,0};
    #pragma unroll
    for (int rblk = 0; rblk < 4; ++rblk) {
        int k = rblk * 32 + lane;
        if (k < HIDN) {
            float hA = __ldg(&b1[k]);
            float hB = hA;
            #pragma unroll
            for (int f = 0; f < 10; ++f) {
                float w = __ldg(&W1[f * HIDN + k]);
                hA = fmaf(featA[f], w, hA);
                hB = fmaf(featB[f], w, hB);
            }
            hA = (hA >= 0.0f) ? hA : 0.1f * hA;
            hB = (hB >= 0.0f) ? hB : 0.1f * hB;
            #pragma unroll
            for (int m = 0; m < 6; ++m) {
                float w = __ldg(&gW2T[m * HIDN + k]);
                poA[m] = fmaf(hA, w, poA[m]);
                poB[m] = fmaf(hB, w, poB[m]);
            }
        }
    }
    #pragma unroll
    for (int o = 16; o; o >>= 1) {
        #pragma unroll
        for (int m = 0; m < 6; ++m) {
            poA[m] += __shfl_xor_sync(0xffffffffu, poA[m], o);
            poB[m] += __shfl_xor_sync(0xffffffffu, poB[m], o);
        }
    }

    // ---- epilogue (lane 0 writes both particles) ----
    if (lane == 0) {
        float* opA = out + ((size_t)b * NPART + i0) * 6;
        float oA[6];
        #pragma unroll
        for (int m = 0; m < 6; ++m) oA[m] = poA[m] + __ldg(&b2[m]);
        opA[0] = yiA  + 0.1f * oA[0];
        opA[1] = xiA  + 0.1f * oA[1];
        opA[2] = tauA + 0.1f * oA[2];
        opA[3] = sigA + 0.1f * oA[3];
        float sp4 = fmaxf(oA[4], 0.0f) + log1pf(expf(-fabsf(oA[4])));
        float sp5 = fmaxf(oA[5], 0.0f) + log1pf(expf(-fabsf(oA[5])));
        opA[4] = 0.1f * sp4;
        opA[5] = 0.1f * sp5;

        float* opB = out + ((size_t)b * NPART + i1) * 6;
        float oB[6];
        #pragma unroll
        for (int m = 0; m < 6; ++m) oB[m] = poB[m] + __ldg(&b2[m]);
        opB[0] = yiB  + 0.1f * oB[0];
        opB[1] = xiB  + 0.1f * oB[1];
        opB[2] = tauB + 0.1f * oB[2];
        opB[3] = sigB + 0.1f * oB[3];
        float sq4 = fmaxf(oB[4], 0.0f) + log1pf(expf(-fabsf(oB[4])));
        float sq5 = fmaxf(oB[5], 0.0f) + log1pf(expf(-fabsf(oB[5])));
        opB[4] = 0.1f * sq4;
        opB[5] = 0.1f * sq5;
    }
}

extern "C" void kernel_launch(void* const* d_in, const int* in_sizes, int n_in,
                              void* d_out, int out_size)
{
    const float* inp = (const float*)d_in[0];  // (16,512,6)
    const float* W1  = (const float*)d_in[1];  // (10,100)
    const float* b1  = (const float*)d_in[2];  // (100,)
    const float* W2  = (const float*)d_in[3];  // (100,6)
    const float* b2  = (const float*)d_in[4];  // (6,)
    float* out = (float*)d_out;                // (16,512,6)

    // 1) pack per-particle constants + W2 transpose into device-global scratch
    prep_kernel<<<(NB * NPART + TPB - 1) / TPB, TPB>>>(inp, W2);
    // 2) main fused kernel: 1024 blocks, prologue-free, 8 CTAs/SM
    dim3 grid(NB * (NPART / (WPB * NI)));
    vortex_main_kernel<<<grid, TPB>>>(inp, W1, b1, b2, out);
}

// round 7
// speedup vs baseline: 1.1848x; 1.1848x over previous
#include <cuda_runtime.h>
#include <math.h>

#define NPART 512
#define NB    16
#define HIDN  100
#define WPB   4            // warps per block (main kernel)
#define NI    2            // particles i per warp
#define TPB   128

typedef unsigned long long u64;

// ---- device-global scratch (no allocations allowed) ----
// pair-interleaved packed per-j constants; gP*[b*256+idx] covers j=2*idx,2*idx+1
// gP0 = { -y pair, -x pair }  gP1 = { ml2e pair, mc pair }  gP2 = { md pair, tau/2pi pair }
__device__ ulonglong2 gP0[NB * NPART / 2];
__device__ ulonglong2 gP1[NB * NPART / 2];
__device__ ulonglong2 gP2[NB * NPART / 2];
__device__ float      gW2T[6 * HIDN];      // gW2T[m*HIDN+k] = W2[k*6+m]

__device__ __forceinline__ float ex2f(float x) {
    float y; asm("ex2.approx.ftz.f32 %0, %1;" : "=f"(y) : "f"(x)); return y;
}
__device__ __forceinline__ float lg2f(float x) {
    float y; asm("lg2.approx.ftz.f32 %0, %1;" : "=f"(y) : "f"(x)); return y;
}
__device__ __forceinline__ float rsq_a(float x) {
    float y; asm("rsqrt.approx.ftz.f32 %0, %1;" : "=f"(y) : "f"(x)); return y;
}
__device__ __forceinline__ float rcp_a(float x) {
    float y; asm("rcp.approx.ftz.f32 %0, %1;" : "=f"(y) : "f"(x)); return y;
}

// fast softplus: max(x,0) + ln(1+exp(-|x|)) via ex2/lg2
__device__ __forceinline__ float softplus_fast(float x) {
    const float L2E = 1.4426950408889634f;
    const float LN2 = 0.6931471805599453f;
    float e = ex2f(-fabsf(x) * L2E);           // exp(-|x|)
    float l = lg2f(1.0f + e) * LN2;            // log1p(e)
    return fmaxf(x, 0.0f) + l;
}

// ---- packed f32x2 helpers (sm_100+) ----
__device__ __forceinline__ u64 pk2(float lo, float hi) {
    u64 d; asm("mov.b64 %0, {%1, %2};" : "=l"(d) : "f"(lo), "f"(hi)); return d;
}
__device__ __forceinline__ void upk2(u64 v, float& lo, float& hi) {
    asm("mov.b64 {%0, %1}, %2;" : "=f"(lo), "=f"(hi) : "l"(v));
}
__device__ __forceinline__ u64 fma2(u64 a, u64 b, u64 c) {
    u64 d; asm("fma.rn.f32x2 %0, %1, %2, %3;" : "=l"(d) : "l"(a), "l"(b), "l"(c)); return d;
}
__device__ __forceinline__ u64 mul2(u64 a, u64 b) {
    u64 d; asm("mul.rn.f32x2 %0, %1, %2;" : "=l"(d) : "l"(a), "l"(b)); return d;
}
__device__ __forceinline__ u64 add2(u64 a, u64 b) {
    u64 d; asm("add.rn.f32x2 %0, %1, %2;" : "=l"(d) : "l"(a), "l"(b)); return d;
}
__device__ __forceinline__ u64 ex2p(u64 a) {
    float lo, hi; upk2(a, lo, hi);
    return pk2(ex2f(lo), ex2f(hi));
}
__device__ __forceinline__ u64 rsqp(u64 a) {
    float lo, hi; upk2(a, lo, hi);
    return pk2(rsq_a(lo), rsq_a(hi));
}

struct Acc { u64 vyp, vx, F, G, Gxx, Gyy; };

// per-pair vortex interaction (packed 2 j's). Accumulates vyp = +Sum F*dx
// (vy = -vyp, negated in feature assembly).
__device__ __forceinline__ void pair_body(
    u64 yi2, u64 xi2, const ulonglong2& q0, const ulonglong2& q1,
    const ulonglong2& q2, u64 is2v, u64 nhcv, u64 nddv, Acc& a,
    u64 ones, u64 nones, u64 eps2)
{
    u64 dy  = add2(yi2, q0.x);                 // yi - yj
    u64 dx  = add2(xi2, q0.y);                 // xi - xj
    u64 sq  = fma2(dy, dy, mul2(dx, dx));
    u64 s   = add2(sq, eps2);
    u64 rs  = rsqp(s);                         // 1/sqrt(s)
    u64 r   = mul2(s, rs);                     // sqrt(s)
    u64 ivs = mul2(rs, rs);                    // 1/s
    u64 e1  = ex2p(mul2(sq, q1.x));            // exp(-sq/sig^2)
    u64 e2  = ex2p(fma2(q1.y, r, mul2(q2.x, sq))); // exp(-c r - d sq)
    u64 g   = fma2(e1, nones, ones);           // 1 - e1 (== 0 for j==i)
    u64 A   = mul2(q2.y, ivs);                 // tau/(2 pi s)
    u64 Ae2 = mul2(A, e2);
    u64 F   = mul2(Ae2, g);                    // falloff
    u64 is2e1 = mul2(is2v, e1);
    u64 mivs  = fma2(ivs, nones, nddv);        // -d - 1/s
    u64 t2n   = fma2(nhcv, rs, mivs);          // -(c/(2r) + d + 1/s)
    u64 inner = fma2(g, t2n, is2e1);           // is2*e1 - g*t2
    u64 Fp  = mul2(Ae2, inner);                // dF/d(sq)
    u64 G2  = add2(Fp, Fp);
    a.vyp = fma2(F, dx, a.vyp);
    a.vx  = fma2(F, dy, a.vx);
    a.F   = add2(a.F, F);
    u64 gdy = mul2(G2, dy);
    u64 gdx = mul2(G2, dx);
    a.G   = fma2(gdy, dx, a.G);
    a.Gxx = fma2(gdx, dx, a.Gxx);
    a.Gyy = fma2(gdy, dy, a.Gyy);
}

// ---- precompute kernel: packs per-particle constants + W2 transpose ----
__global__ __launch_bounds__(TPB)
void prep_kernel(const float* __restrict__ inp, const float* __restrict__ W2)
{
    const float L2E    = 1.4426950408889634f;
    const float INV2PI = 0.15915494309189535f;
    int p = blockIdx.x * blockDim.x + threadIdx.x;   // 0..8191
    if (p < NB * NPART) {
        float y   = inp[p * 6 + 0];
        float x   = inp[p * 6 + 1];
        float tau = inp[p * 6 + 2];
        float sig = inp[p * 6 + 3];
        float c   = inp[p * 6 + 4];
        float d   = inp[p * 6 + 5];
        float is2 = rcp_a(sig * sig);
        int idx = p >> 1;                             // global pair index
        int o   = p & 1;
        float* f0 = (float*)gP0;
        float* f1 = (float*)gP1;
        float* f2 = (float*)gP2;
        f0[idx * 4 + 0 + o] = -y;
        f0[idx * 4 + 2 + o] = -x;
        f1[idx * 4 + 0 + o] = -is2 * L2E;   // ml2e
        f1[idx * 4 + 2 + o] = -c * L2E;     // mc
        f2[idx * 4 + 0 + o] = -d * L2E;     // md
        f2[idx * 4 + 2 + o] = tau * INV2PI; // t2p
    }
    if (p < HIDN * 6) {
        int k = p / 6, m = p % 6;
        gW2T[m * HIDN + k] = W2[p];
    }
}

// ---- main kernel: no shared memory, no syncthreads ----
__global__ __launch_bounds__(TPB, 7)
void vortex_main_kernel(const float* __restrict__ inp,
                        const float* __restrict__ W1,
                        const float* __restrict__ b1,
                        const float* __restrict__ b2,
                        float* __restrict__ out)
{
    const int tid  = threadIdx.x;
    const int ipb  = WPB * NI;                 // 8 i's per block
    const int bpb  = NPART / ipb;              // 64 blocks per batch
    const int b    = blockIdx.x / bpb;
    const int ig   = blockIdx.x % bpb;
    const int warp = tid >> 5;
    const int lane = tid & 31;
    const int i0   = ig * ipb + warp * NI;
    const int i1   = i0 + 1;

    const float LN2 = 0.6931471805599453f;

    const float* pA = inp + ((size_t)b * NPART + i0) * 6;
    const float* pB = inp + ((size_t)b * NPART + i1) * 6;
    const float yiA = __ldg(pA + 0), xiA = __ldg(pA + 1);
    const float yiB = __ldg(pB + 0), xiB = __ldg(pB + 1);

    const ulonglong2* __restrict__ P0 = gP0 + (size_t)b * (NPART / 2);
    const ulonglong2* __restrict__ P1 = gP1 + (size_t)b * (NPART / 2);
    const ulonglong2* __restrict__ P2 = gP2 + (size_t)b * (NPART / 2);

    const u64 yA = pk2(yiA, yiA), xA = pk2(xiA, xiA);
    const u64 yB = pk2(yiB, yiB), xB = pk2(xiB, xiB);
    const u64 ones  = pk2(1.0f, 1.0f);
    const u64 nones = pk2(-1.0f, -1.0f);
    const u64 eps2  = pk2(1e-6f, 1e-6f);
    const u64 nln2  = pk2(-LN2, -LN2);
    const u64 pln2  = pk2(LN2, LN2);
    const u64 phln2 = pk2(0.5f * LN2, 0.5f * LN2);

    Acc accA = {0,0,0,0,0,0};
    Acc accB = {0,0,0,0,0,0};

    #pragma unroll 4
    for (int jj = 0; jj < NPART / 64; ++jj) {
        int idx = jj * 32 + lane;
        ulonglong2 q0 = P0[idx];
        ulonglong2 q1 = P1[idx];
        ulonglong2 q2 = P2[idx];
        u64 is2v = mul2(q1.x, nln2);           // is2 = -ml2e * ln2
        u64 nhcv = mul2(q1.y, phln2);          // -c/2 = mc * ln2/2
        u64 nddv = mul2(q2.x, pln2);           // -d   = md * ln2
        pair_body(yA, xA, q0, q1, q2, is2v, nhcv, nddv, accA, ones, nones, eps2);
        pair_body(yB, xB, q0, q1, q2, is2v, nhcv, nddv, accB, ones, nones, eps2);
    }

    // ---- horizontal add of packed halves, then warp butterfly reduce ----
    float red[12];
    {
        float l, h;
        upk2(accA.vyp, l, h); red[0]  = l + h;
        upk2(accA.vx,  l, h); red[1]  = l + h;
        upk2(accA.F,   l, h); red[2]  = l + h;
        upk2(accA.G,   l, h); red[3]  = l + h;
        upk2(accA.Gxx, l, h); red[4]  = l + h;
        upk2(accA.Gyy, l, h); red[5]  = l + h;
        upk2(accB.vyp, l, h); red[6]  = l + h;
        upk2(accB.vx,  l, h); red[7]  = l + h;
        upk2(accB.F,   l, h); red[8]  = l + h;
        upk2(accB.G,   l, h); red[9]  = l + h;
        upk2(accB.Gxx, l, h); red[10] = l + h;
        upk2(accB.Gyy, l, h); red[11] = l + h;
    }
    #pragma unroll
    for (int o = 16; o; o >>= 1) {
        #pragma unroll
        for (int m = 0; m < 12; ++m)
            red[m] += __shfl_xor_sync(0xffffffffu, red[m], o);
    }

    // per-i scalars (loaded late to keep mainloop registers lean; L1/L2 hit)
    const float tauA = __ldg(pA + 2), sigA = __ldg(pA + 3);
    const float cA   = __ldg(pA + 4), dA   = __ldg(pA + 5);
    const float tauB = __ldg(pB + 2), sigB = __ldg(pB + 3);
    const float cB   = __ldg(pB + 4), dB   = __ldg(pB + 5);

    // features: tau, sig, c, d, vy, vx, dvy/dy, dvy/dx, dvx/dy, dvx/dx
    float featA[10], featB[10];
    featA[0] = tauA;    featA[1] = sigA;  featA[2] = cA;  featA[3] = dA;
    featA[4] = -red[0];            // vy = -Sum F dx
    featA[5] = red[1];
    featA[6] = -red[3];            // dvy/dy
    featA[7] = -(red[4] + red[2]); // dvy/dx
    featA[8] = red[5] + red[2];    // dvx/dy
    featA[9] = red[3];             // dvx/dx
    featB[0] = tauB;    featB[1] = sigB;  featB[2] = cB;  featB[3] = dB;
    featB[4] = -red[6];
    featB[5] = red[7];
    featB[6] = -red[9];
    featB[7] = -(red[10] + red[8]);
    featB[8] = red[11] + red[8];
    featB[9] = red[9];

    // ---- MLP 10 -> 100 (LeakyReLU 0.1) -> 6, weights via L1-hot LDG ----
    float poA[6] = {0,0,0,0,0,0};
    float poB[6] = {0,0,0,0,0,0};
    #pragma unroll
    for (int rblk = 0; rblk < 4; ++rblk) {
        int k = rblk * 32 + lane;
        if (k < HIDN) {
            float hA = __ldg(&b1[k]);
            float hB = hA;
            #pragma unroll
            for (int f = 0; f < 10; ++f) {
                float w = __ldg(&W1[f * HIDN + k]);
                hA = fmaf(featA[f], w, hA);
                hB = fmaf(featB[f], w, hB);
            }
            hA = (hA >= 0.0f) ? hA : 0.1f * hA;
            hB = (hB >= 0.0f) ? hB : 0.1f * hB;
            #pragma unroll
            for (int m = 0; m < 6; ++m) {
                float w = __ldg(&gW2T[m * HIDN + k]);
                poA[m] = fmaf(hA, w, poA[m]);
                poB[m] = fmaf(hB, w, poB[m]);
            }
        }
    }
    #pragma unroll
    for (int o = 16; o; o >>= 1) {
        #pragma unroll
        for (int m = 0; m < 6; ++m) {
            poA[m] += __shfl_xor_sync(0xffffffffu, poA[m], o);
            poB[m] += __shfl_xor_sync(0xffffffffu, poB[m], o);
        }
    }

    // ---- epilogue (lane 0 writes both particles, float2 stores) ----
    if (lane == 0) {
        float bb0 = __ldg(&b2[0]), bb1 = __ldg(&b2[1]), bb2 = __ldg(&b2[2]);
        float bb3 = __ldg(&b2[3]), bb4 = __ldg(&b2[4]), bb5 = __ldg(&b2[5]);

        float2* opA = (float2*)(out + ((size_t)b * NPART + i0) * 6);
        opA[0] = make_float2(yiA  + 0.1f * (poA[0] + bb0),
                             xiA  + 0.1f * (poA[1] + bb1));
        opA[1] = make_float2(tauA + 0.1f * (poA[2] + bb2),
                             sigA + 0.1f * (poA[3] + bb3));
        opA[2] = make_float2(0.1f * softplus_fast(poA[4] + bb4),
                             0.1f * softplus_fast(poA[5] + bb5));

        float2* opB = (float2*)(out + ((size_t)b * NPART + i1) * 6);
        opB[0] = make_float2(yiB  + 0.1f * (poB[0] + bb0),
                             xiB  + 0.1f * (poB[1] + bb1));
        opB[1] = make_float2(tauB + 0.1f * (poB[2] + bb2),
                             sigB + 0.1f * (poB[3] + bb3));
        opB[2] = make_float2(0.1f * softplus_fast(poB[4] + bb4),
                             0.1f * softplus_fast(poB[5] + bb5));
    }
}

extern "C" void kernel_launch(void* const* d_in, const int* in_sizes, int n_in,
                              void* d_out, int out_size)
{
    const float* inp = (const float*)d_in[0];  // (16,512,6)
    const float* W1  = (const float*)d_in[1];  // (10,100)
    const float* b1  = (const float*)d_in[2];  // (100,)
    const float* W2  = (const float*)d_in[3];  // (100,6)
    const float* b2  = (const float*)d_in[4];  // (6,)
    float* out = (float*)d_out;                // (16,512,6)

    // 1) pack per-particle constants + W2 transpose into device-global scratch
    prep_kernel<<<(NB * NPART + TPB - 1) / TPB, TPB>>>(inp, W2);
    // 2) main fused kernel: 1024 blocks, prologue-free
    dim3 grid(NB * (NPART / (WPB * NI)));
    vortex_main_kernel<<<grid, TPB>>>(inp, W1, b1, b2, out);
}

// round 8
// speedup vs baseline: 1.2071x; 1.0188x over previous
#include <cuda_runtime.h>
#include <math.h>

#define NPART 512
#define NB    16
#define HIDN  100
#define WPB   2            // warps per block (main kernel)
#define NI    4            // particles i per warp
#define TPB   64

typedef unsigned long long u64;

// ---- device-global scratch (no allocations allowed) ----
// pair-interleaved packed per-j constants; gP*[b*256+idx] covers j=2*idx,2*idx+1
// gP0 = { -y pair, -x pair }  gP1 = { ml2e pair, mc pair }  gP2 = { md pair, tau/2pi pair }
__device__ ulonglong2 gP0[NB * NPART / 2];
__device__ ulonglong2 gP1[NB * NPART / 2];
__device__ ulonglong2 gP2[NB * NPART / 2];
__device__ float      gW2T[6 * HIDN];      // gW2T[m*HIDN+k] = W2[k*6+m]

__device__ __forceinline__ float ex2f(float x) {
    float y; asm("ex2.approx.ftz.f32 %0, %1;" : "=f"(y) : "f"(x)); return y;
}
__device__ __forceinline__ float lg2f(float x) {
    float y; asm("lg2.approx.ftz.f32 %0, %1;" : "=f"(y) : "f"(x)); return y;
}
__device__ __forceinline__ float rsq_a(float x) {
    float y; asm("rsqrt.approx.ftz.f32 %0, %1;" : "=f"(y) : "f"(x)); return y;
}
__device__ __forceinline__ float rcp_a(float x) {
    float y; asm("rcp.approx.ftz.f32 %0, %1;" : "=f"(y) : "f"(x)); return y;
}

// fast softplus: max(x,0) + ln(1+exp(-|x|)) via ex2/lg2
__device__ __forceinline__ float softplus_fast(float x) {
    const float L2E = 1.4426950408889634f;
    const float LN2 = 0.6931471805599453f;
    float e = ex2f(-fabsf(x) * L2E);
    float l = lg2f(1.0f + e) * LN2;
    return fmaxf(x, 0.0f) + l;
}

// ---- packed f32x2 helpers (sm_100+) ----
__device__ __forceinline__ u64 pk2(float lo, float hi) {
    u64 d; asm("mov.b64 %0, {%1, %2};" : "=l"(d) : "f"(lo), "f"(hi)); return d;
}
__device__ __forceinline__ void upk2(u64 v, float& lo, float& hi) {
    asm("mov.b64 {%0, %1}, %2;" : "=f"(lo), "=f"(hi) : "l"(v));
}
__device__ __forceinline__ u64 fma2(u64 a, u64 b, u64 c) {
    u64 d; asm("fma.rn.f32x2 %0, %1, %2, %3;" : "=l"(d) : "l"(a), "l"(b), "l"(c)); return d;
}
__device__ __forceinline__ u64 mul2(u64 a, u64 b) {
    u64 d; asm("mul.rn.f32x2 %0, %1, %2;" : "=l"(d) : "l"(a), "l"(b)); return d;
}
__device__ __forceinline__ u64 add2(u64 a, u64 b) {
    u64 d; asm("add.rn.f32x2 %0, %1, %2;" : "=l"(d) : "l"(a), "l"(b)); return d;
}
__device__ __forceinline__ u64 ex2p(u64 a) {
    float lo, hi; upk2(a, lo, hi);
    return pk2(ex2f(lo), ex2f(hi));
}
__device__ __forceinline__ u64 rsqp(u64 a) {
    float lo, hi; upk2(a, lo, hi);
    return pk2(rsq_a(lo), rsq_a(hi));
}

struct Acc { u64 vyp, vx, F, G, Gxx, Gyy; };

// per-pair vortex interaction (packed 2 j's). Accumulates vyp = +Sum F*dx.
__device__ __forceinline__ void pair_body(
    u64 yi2, u64 xi2, const ulonglong2& q0, const ulonglong2& q1,
    const ulonglong2& q2, u64 is2v, u64 nhcv, u64 nddv, Acc& a,
    u64 ones, u64 nones, u64 eps2)
{
    u64 dy  = add2(yi2, q0.x);                 // yi - yj
    u64 dx  = add2(xi2, q0.y);                 // xi - xj
    u64 sq  = fma2(dy, dy, mul2(dx, dx));
    u64 s   = add2(sq, eps2);
    u64 rs  = rsqp(s);                         // 1/sqrt(s)
    u64 r   = mul2(s, rs);                     // sqrt(s)
    u64 ivs = mul2(rs, rs);                    // 1/s
    u64 e1  = ex2p(mul2(sq, q1.x));            // exp(-sq/sig^2)
    u64 e2  = ex2p(fma2(q1.y, r, mul2(q2.x, sq))); // exp(-c r - d sq)
    u64 g   = fma2(e1, nones, ones);           // 1 - e1 (== 0 for j==i)
    u64 A   = mul2(q2.y, ivs);                 // tau/(2 pi s)
    u64 Ae2 = mul2(A, e2);
    u64 F   = mul2(Ae2, g);                    // falloff
    u64 is2e1 = mul2(is2v, e1);
    u64 mivs  = fma2(ivs, nones, nddv);        // -d - 1/s
    u64 t2n   = fma2(nhcv, rs, mivs);          // -(c/(2r) + d + 1/s)
    u64 inner = fma2(g, t2n, is2e1);           // is2*e1 - g*t2
    u64 Fp  = mul2(Ae2, inner);                // dF/d(sq)
    u64 G2  = add2(Fp, Fp);
    a.vyp = fma2(F, dx, a.vyp);
    a.vx  = fma2(F, dy, a.vx);
    a.F   = add2(a.F, F);
    u64 gdy = mul2(G2, dy);
    u64 gdx = mul2(G2, dx);
    a.G   = fma2(gdy, dx, a.G);
    a.Gxx = fma2(gdx, dx, a.Gxx);
    a.Gyy = fma2(gdy, dy, a.Gyy);
}

// ---- precompute kernel: packs per-particle constants + W2 transpose ----
__global__ __launch_bounds__(128)
void prep_kernel(const float* __restrict__ inp, const float* __restrict__ W2)
{
    const float L2E    = 1.4426950408889634f;
    const float INV2PI = 0.15915494309189535f;
    int p = blockIdx.x * blockDim.x + threadIdx.x;   // 0..8191
    if (p < NB * NPART) {
        float y   = inp[p * 6 + 0];
        float x   = inp[p * 6 + 1];
        float tau = inp[p * 6 + 2];
        float sig = inp[p * 6 + 3];
        float c   = inp[p * 6 + 4];
        float d   = inp[p * 6 + 5];
        float is2 = rcp_a(sig * sig);
        int idx = p >> 1;
        int o   = p & 1;
        float* f0 = (float*)gP0;
        float* f1 = (float*)gP1;
        float* f2 = (float*)gP2;
        f0[idx * 4 + 0 + o] = -y;
        f0[idx * 4 + 2 + o] = -x;
        f1[idx * 4 + 0 + o] = -is2 * L2E;   // ml2e
        f1[idx * 4 + 2 + o] = -c * L2E;     // mc
        f2[idx * 4 + 0 + o] = -d * L2E;     // md
        f2[idx * 4 + 2 + o] = tau * INV2PI; // t2p
    }
    if (p < HIDN * 6) {
        int k = p / 6, m = p % 6;
        gW2T[m * HIDN + k] = W2[p];
    }
}

// ---- main kernel: 64 threads, 4 particles per warp, reg-rich for ILP ----
__global__ __launch_bounds__(TPB, 7)
void vortex_main_kernel(const float* __restrict__ inp,
                        const float* __restrict__ W1,
                        const float* __restrict__ b1,
                        const float* __restrict__ b2,
                        float* __restrict__ out)
{
    const int tid   = threadIdx.x;
    const int ipb   = WPB * NI;                // 8 i's per block
    const int bpb   = NPART / ipb;             // 64 blocks per batch
    const int b     = blockIdx.x / bpb;
    const int ig    = blockIdx.x % bpb;
    const int warp  = tid >> 5;
    const int lane  = tid & 31;
    const int ibase = ig * ipb + warp * NI;    // this warp's first particle

    const float LN2 = 0.6931471805599453f;

    const float* pp[NI];
    float yi[NI], xi[NI];
    u64 yp[NI], xp[NI];
    #pragma unroll
    for (int q = 0; q < NI; ++q) {
        pp[q] = inp + ((size_t)b * NPART + ibase + q) * 6;
        yi[q] = __ldg(pp[q] + 0);
        xi[q] = __ldg(pp[q] + 1);
        yp[q] = pk2(yi[q], yi[q]);
        xp[q] = pk2(xi[q], xi[q]);
    }

    const ulonglong2* __restrict__ P0 = gP0 + (size_t)b * (NPART / 2);
    const ulonglong2* __restrict__ P1 = gP1 + (size_t)b * (NPART / 2);
    const ulonglong2* __restrict__ P2 = gP2 + (size_t)b * (NPART / 2);

    const u64 ones  = pk2(1.0f, 1.0f);
    const u64 nones = pk2(-1.0f, -1.0f);
    const u64 eps2  = pk2(1e-6f, 1e-6f);
    const u64 nln2  = pk2(-LN2, -LN2);
    const u64 pln2  = pk2(LN2, LN2);
    const u64 phln2 = pk2(0.5f * LN2, 0.5f * LN2);

    Acc acc[NI];
    #pragma unroll
    for (int q = 0; q < NI; ++q) acc[q] = (Acc){0,0,0,0,0,0};

    #pragma unroll 2
    for (int jj = 0; jj < NPART / 64; ++jj) {
        int idx = jj * 32 + lane;
        ulonglong2 q0 = P0[idx];
        ulonglong2 q1 = P1[idx];
        ulonglong2 q2 = P2[idx];
        u64 is2v = mul2(q1.x, nln2);           // is2 = -ml2e * ln2
        u64 nhcv = mul2(q1.y, phln2);          // -c/2 = mc * ln2/2
        u64 nddv = mul2(q2.x, pln2);           // -d   = md * ln2
        #pragma unroll
        for (int q = 0; q < NI; ++q)
            pair_body(yp[q], xp[q], q0, q1, q2, is2v, nhcv, nddv, acc[q],
                      ones, nones, eps2);
    }

    // ---- horizontal add of packed halves, then warp butterfly reduce ----
    float red[6 * NI];
    #pragma unroll
    for (int q = 0; q < NI; ++q) {
        float l, h;
        upk2(acc[q].vyp, l, h); red[q * 6 + 0] = l + h;
        upk2(acc[q].vx,  l, h); red[q * 6 + 1] = l + h;
        upk2(acc[q].F,   l, h); red[q * 6 + 2] = l + h;
        upk2(acc[q].G,   l, h); red[q * 6 + 3] = l + h;
        upk2(acc[q].Gxx, l, h); red[q * 6 + 4] = l + h;
        upk2(acc[q].Gyy, l, h); red[q * 6 + 5] = l + h;
    }
    #pragma unroll
    for (int o = 16; o; o >>= 1) {
        #pragma unroll
        for (int m = 0; m < 6 * NI; ++m)
            red[m] += __shfl_xor_sync(0xffffffffu, red[m], o);
    }

    // per-i scalars + feature vectors
    // features: tau, sig, c, d, vy, vx, dvy/dy, dvy/dx, dvx/dy, dvx/dx
    float feat[NI][10];
    float tau_[NI], sig_[NI];
    #pragma unroll
    for (int q = 0; q < NI; ++q) {
        tau_[q] = __ldg(pp[q] + 2);
        sig_[q] = __ldg(pp[q] + 3);
        feat[q][0] = tau_[q];
        feat[q][1] = sig_[q];
        feat[q][2] = __ldg(pp[q] + 4);
        feat[q][3] = __ldg(pp[q] + 5);
        feat[q][4] = -red[q * 6 + 0];                    // vy
        feat[q][5] = red[q * 6 + 1];                     // vx
        feat[q][6] = -red[q * 6 + 3];                    // dvy/dy
        feat[q][7] = -(red[q * 6 + 4] + red[q * 6 + 2]); // dvy/dx
        feat[q][8] = red[q * 6 + 5] + red[q * 6 + 2];    // dvx/dy
        feat[q][9] = red[q * 6 + 3];                     // dvx/dx
    }

    // ---- MLP 10 -> 100 (LeakyReLU 0.1) -> 6, weights shared across 4 i's ----
    float po[NI][6];
    #pragma unroll
    for (int q = 0; q < NI; ++q)
        #pragma unroll
        for (int m = 0; m < 6; ++m) po[q][m] = 0.0f;

    #pragma unroll
    for (int rblk = 0; rblk < 4; ++rblk) {
        int k = rblk * 32 + lane;
        if (k < HIDN) {
            float h[NI];
            float bb = __ldg(&b1[k]);
            #pragma unroll
            for (int q = 0; q < NI; ++q) h[q] = bb;
            #pragma unroll
            for (int f = 0; f < 10; ++f) {
                float w = __ldg(&W1[f * HIDN + k]);
                #pragma unroll
                for (int q = 0; q < NI; ++q) h[q] = fmaf(feat[q][f], w, h[q]);
            }
            #pragma unroll
            for (int q = 0; q < NI; ++q)
                h[q] = (h[q] >= 0.0f) ? h[q] : 0.1f * h[q];
            #pragma unroll
            for (int m = 0; m < 6; ++m) {
                float w = __ldg(&gW2T[m * HIDN + k]);
                #pragma unroll
                for (int q = 0; q < NI; ++q) po[q][m] = fmaf(h[q], w, po[q][m]);
            }
        }
    }
    #pragma unroll
    for (int o = 16; o; o >>= 1) {
        #pragma unroll
        for (int q = 0; q < NI; ++q)
            #pragma unroll
            for (int m = 0; m < 6; ++m)
                po[q][m] += __shfl_xor_sync(0xffffffffu, po[q][m], o);
    }

    // ---- epilogue (lane 0 writes all 4 particles, float2 stores) ----
    if (lane == 0) {
        float bb0 = __ldg(&b2[0]), bb1 = __ldg(&b2[1]), bb2 = __ldg(&b2[2]);
        float bb3 = __ldg(&b2[3]), bb4 = __ldg(&b2[4]), bb5 = __ldg(&b2[5]);
        #pragma unroll
        for (int q = 0; q < NI; ++q) {
            float2* op = (float2*)(out + ((size_t)b * NPART + ibase + q) * 6);
            op[0] = make_float2(yi[q]   + 0.1f * (po[q][0] + bb0),
                                xi[q]   + 0.1f * (po[q][1] + bb1));
            op[1] = make_float2(tau_[q] + 0.1f * (po[q][2] + bb2),
                                sig_[q] + 0.1f * (po[q][3] + bb3));
            op[2] = make_float2(0.1f * softplus_fast(po[q][4] + bb4),
                                0.1f * softplus_fast(po[q][5] + bb5));
        }
    }
}

extern "C" void kernel_launch(void* const* d_in, const int* in_sizes, int n_in,
                              void* d_out, int out_size)
{
    const float* inp = (const float*)d_in[0];  // (16,512,6)
    const float* W1  = (const float*)d_in[1];  // (10,100)
    const float* b1  = (const float*)d_in[2];  // (100,)
    const float* W2  = (const float*)d_in[3];  // (100,6)
    const float* b2  = (const float*)d_in[4];  // (6,)
    float* out = (float*)d_out;                // (16,512,6)

    // 1) pack per-particle constants + W2 transpose into device-global scratch
    prep_kernel<<<(NB * NPART + 127) / 128, 128>>>(inp, W2);
    // 2) main fused kernel: 1024 blocks of 64 threads, 4 particles/warp
    dim3 grid(NB * (NPART / (WPB * NI)));      // 1024
    vortex_main_kernel<<<grid, TPB>>>(inp, W1, b1, b2, out);
}